// round 1
// baseline (speedup 1.0000x reference)
#include <cuda_runtime.h>
#include <cstdint>

#define N_GRAPH   4096
#define NPG       32
#define N_NODES   (N_GRAPH * NPG)      // 131072
#define N_EDGES   (N_NODES * 16)      // 2097152
#define INV_SQRT3 0.57735026918962576451f
#define INV_SQRT2 0.70710678118654752440f

// ---------------- scratch (static device arrays; no runtime alloc) ----------
__device__ __align__(16) float g_x0a[N_NODES * 4];    // initial scalar feats
__device__ __align__(16) float g_a0 [N_NODES * 4];    // L1 accum l=0
__device__ __align__(16) float g_a1 [N_NODES * 12];   // L1 accum l=1 (4ch x 3)
__device__ __align__(16) float g_x0b[N_NODES * 4];    // after si2+gate
__device__ __align__(16) float g_x1b[N_NODES * 12];
__device__ __align__(16) float g_b0 [N_NODES * 8];    // L2 accum l=0 (concat 4+4)
__device__ __align__(16) float g_b1 [N_NODES * 36];   // L2 accum l=1 (12ch x 3)
__device__ __align__(16) float g_x0c[N_NODES * 4];    // after si3+gate
__device__ __align__(16) float g_x1c[N_NODES * 12];
__device__ __align__(16) float g_c0 [N_NODES * 8];    // L3 accum l=0 (concat 4+4)

// ---------------- helpers ---------------------------------------------------
__device__ __forceinline__ void red4(float* p, float a, float b, float c, float d) {
    asm volatile("red.global.add.v4.f32 [%0], {%1,%2,%3,%4};"
                 :: "l"(p), "f"(a), "f"(b), "f"(c), "f"(d) : "memory");
}

__device__ __forceinline__ float sigmoidf(float x) {
    return 1.0f / (1.0f + __expf(-x));
}

// compute unit vector + rbf for one edge
__device__ __forceinline__ void edge_geom(const float* __restrict__ pos,
                                          int s, int r, float u[3], float rbf[8]) {
    float sx = pos[3*s+0], sy = pos[3*s+1], sz = pos[3*s+2];
    float rx = pos[3*r+0], ry = pos[3*r+1], rz = pos[3*r+2];
    float dx = rx - sx, dy = ry - sy, dz = rz - sz;
    float d2 = dx*dx + dy*dy + dz*dz;
    float dist = sqrtf(d2);
    float inv = 1.0f / fmaxf(dist, 1e-9f);
    u[0] = dx * inv; u[1] = dy * inv; u[2] = dz * inv;
#pragma unroll
    for (int b = 0; b < 8; b++) {
        float t = dist - 0.5f * (float)b;       // centers = linspace(0,3.5,8)
        rbf[b] = __expf(-4.0f * t * t);
    }
}

// one radial path: R[4] = relu(rbf @ w1[p] + b1[p]) @ w2[p] + b2[p]
__device__ __forceinline__ void radial(int p, const float rbf[8], float R[4],
                                       const float* sw1, const float* sb1,
                                       const float* sw2, const float* sb2) {
    float h[8];
    const float* w1 = sw1 + p * 64;
#pragma unroll
    for (int j = 0; j < 8; j++) h[j] = sb1[p*8 + j];
#pragma unroll
    for (int b = 0; b < 8; b++) {
        float rb = rbf[b];
#pragma unroll
        for (int j = 0; j < 8; j++) h[j] = fmaf(rb, w1[b*8 + j], h[j]);
    }
#pragma unroll
    for (int j = 0; j < 8; j++) h[j] = fmaxf(h[j], 0.0f);
    const float* w2 = sw2 + p * 32;
#pragma unroll
    for (int c = 0; c < 4; c++) R[c] = sb2[p*4 + c];
#pragma unroll
    for (int j = 0; j < 8; j++) {
        float hj = h[j];
#pragma unroll
        for (int c = 0; c < 4; c++) R[c] = fmaf(hj, w2[j*4 + c], R[c]);
    }
}

#define LOAD_RADIAL_SMEM(rw1, rb1, rw2, rb2)                                   \
    __shared__ float sw1[576], sb1[72], sw2[288], sb2[36];                     \
    for (int i = threadIdx.x; i < 576; i += blockDim.x) sw1[i] = rw1[i];       \
    for (int i = threadIdx.x; i < 72;  i += blockDim.x) sb1[i] = rb1[i];       \
    for (int i = threadIdx.x; i < 288; i += blockDim.x) sw2[i] = rw2[i];       \
    for (int i = threadIdx.x; i < 36;  i += blockDim.x) sb2[i] = rb2[i];       \
    __syncthreads();

// ---------------- kernels ---------------------------------------------------

// zero accumulators + initial self-interaction x0 = w_si1 * node_feat
__global__ void k_init(const float* __restrict__ nf, const float* __restrict__ w1) {
    long i0 = (long)blockIdx.x * blockDim.x + threadIdx.x;
    long stride = (long)gridDim.x * blockDim.x;
    float w0 = w1[0], w1v = w1[1], w2v = w1[2], w3v = w1[3];
    for (long i = i0; i < N_NODES; i += stride) {
        float v = nf[i];
        float4 x = make_float4(w0*v, w1v*v, w2v*v, w3v*v);
        ((float4*)g_x0a)[i] = x;
    }
    float4 z = make_float4(0.f, 0.f, 0.f, 0.f);
    for (long i = i0; i < N_NODES;     i += stride) ((float4*)g_a0)[i] = z;
    for (long i = i0; i < N_NODES * 3; i += stride) ((float4*)g_a1)[i] = z;
    for (long i = i0; i < N_NODES * 2; i += stride) ((float4*)g_b0)[i] = z;
    for (long i = i0; i < N_NODES * 9; i += stride) ((float4*)g_b1)[i] = z;
    for (long i = i0; i < N_NODES * 2; i += stride) ((float4*)g_c0)[i] = z;
}

// Layer 1 edges: paths 0 (l0->l0) and 1 (l0->l1)
__global__ void k_edge1(const float* __restrict__ pos,
                        const int* __restrict__ snd, const int* __restrict__ rcv,
                        const float* __restrict__ rw1, const float* __restrict__ rb1,
                        const float* __restrict__ rw2, const float* __restrict__ rb2) {
    LOAD_RADIAL_SMEM(rw1, rb1, rw2, rb2);
    int e = blockIdx.x * blockDim.x + threadIdx.x;
    if (e >= N_EDGES) return;
    int s = snd[e], r = rcv[e];
    float u[3], rbf[8];
    edge_geom(pos, s, r, u, rbf);
    float R0[4], R1[4];
    radial(0, rbf, R0, sw1, sb1, sw2, sb2);
    radial(1, rbf, R1, sw1, sb1, sw2, sb2);
    float4 x0 = ((const float4*)g_x0a)[s];
    float xs[4] = {x0.x, x0.y, x0.z, x0.w};

    red4(&g_a0[r*4], R0[0]*xs[0], R0[1]*xs[1], R0[2]*xs[2], R0[3]*xs[3]);

    float m[12];
#pragma unroll
    for (int c = 0; c < 4; c++) {
        float t = R1[c] * xs[c];
        m[c*3+0] = t*u[0]; m[c*3+1] = t*u[1]; m[c*3+2] = t*u[2];
    }
    float* base = &g_a1[r*12];
    red4(base + 0, m[0], m[1], m[2],  m[3]);
    red4(base + 4, m[4], m[5], m[6],  m[7]);
    red4(base + 8, m[8], m[9], m[10], m[11]);
}

// node update 1: si2 + gate
__global__ void k_node1(const float* __restrict__ w20, const float* __restrict__ w21) {
    int n = blockIdx.x * blockDim.x + threadIdx.x;
    if (n >= N_NODES) return;
    float4 a0 = ((const float4*)g_a0)[n];
    float in0[4] = {a0.x, a0.y, a0.z, a0.w};
    float out0[4];
#pragma unroll
    for (int o = 0; o < 4; o++) {
        float sacc = 0.f;
#pragma unroll
        for (int i = 0; i < 4; i++) sacc = fmaf(__ldg(&w20[o*4+i]), in0[i], sacc);
        out0[o] = sacc * sigmoidf(sacc);
    }
    ((float4*)g_x0b)[n] = make_float4(out0[0], out0[1], out0[2], out0[3]);

    float a1[12];
    float4 t0 = ((const float4*)g_a1)[n*3+0];
    float4 t1 = ((const float4*)g_a1)[n*3+1];
    float4 t2 = ((const float4*)g_a1)[n*3+2];
    a1[0]=t0.x; a1[1]=t0.y; a1[2]=t0.z; a1[3]=t0.w;
    a1[4]=t1.x; a1[5]=t1.y; a1[6]=t1.z; a1[7]=t1.w;
    a1[8]=t2.x; a1[9]=t2.y; a1[10]=t2.z; a1[11]=t2.w;
    float out1[12];
#pragma unroll
    for (int o = 0; o < 4; o++) {
        float vx = 0.f, vy = 0.f, vz = 0.f;
#pragma unroll
        for (int i = 0; i < 4; i++) {
            float w = __ldg(&w21[o*4+i]);
            vx = fmaf(w, a1[i*3+0], vx);
            vy = fmaf(w, a1[i*3+1], vy);
            vz = fmaf(w, a1[i*3+2], vz);
        }
        float nrm = sqrtf(vx*vx + vy*vy + vz*vz);
        float gt = sigmoidf(nrm);
        out1[o*3+0] = vx*gt; out1[o*3+1] = vy*gt; out1[o*3+2] = vz*gt;
    }
    ((float4*)g_x1b)[n*3+0] = make_float4(out1[0], out1[1], out1[2],  out1[3]);
    ((float4*)g_x1b)[n*3+1] = make_float4(out1[4], out1[5], out1[6],  out1[7]);
    ((float4*)g_x1b)[n*3+2] = make_float4(out1[8], out1[9], out1[10], out1[11]);
}

// Layer 2 edges: paths 2..6
__global__ void k_edge2(const float* __restrict__ pos,
                        const int* __restrict__ snd, const int* __restrict__ rcv,
                        const float* __restrict__ rw1, const float* __restrict__ rb1,
                        const float* __restrict__ rw2, const float* __restrict__ rb2) {
    LOAD_RADIAL_SMEM(rw1, rb1, rw2, rb2);
    int e = blockIdx.x * blockDim.x + threadIdx.x;
    if (e >= N_EDGES) return;
    int s = snd[e], r = rcv[e];
    float u[3], rbf[8];
    edge_geom(pos, s, r, u, rbf);

    float4 x0 = ((const float4*)g_x0b)[s];
    float xs[4] = {x0.x, x0.y, x0.z, x0.w};
    float x1[12];
    {
        float4 t0 = ((const float4*)g_x1b)[s*3+0];
        float4 t1 = ((const float4*)g_x1b)[s*3+1];
        float4 t2 = ((const float4*)g_x1b)[s*3+2];
        x1[0]=t0.x; x1[1]=t0.y; x1[2]=t0.z; x1[3]=t0.w;
        x1[4]=t1.x; x1[5]=t1.y; x1[6]=t1.z; x1[7]=t1.w;
        x1[8]=t2.x; x1[9]=t2.y; x1[10]=t2.z; x1[11]=t2.w;
    }

    float R[4];
    // p00_0 : R2 * x0s  -> b0[0:4]
    radial(2, rbf, R, sw1, sb1, sw2, sb2);
    red4(&g_b0[r*8], R[0]*xs[0], R[1]*xs[1], R[2]*xs[2], R[3]*xs[3]);

    // p11_0 : R5 * (x1s . u) / sqrt3  -> b0[4:8]
    radial(5, rbf, R, sw1, sb1, sw2, sb2);
    {
        float d0 = x1[0]*u[0] + x1[1]*u[1] + x1[2]*u[2];
        float d1 = x1[3]*u[0] + x1[4]*u[1] + x1[5]*u[2];
        float d2 = x1[6]*u[0] + x1[7]*u[1] + x1[8]*u[2];
        float d3 = x1[9]*u[0] + x1[10]*u[1] + x1[11]*u[2];
        red4(&g_b0[r*8+4], R[0]*d0*INV_SQRT3, R[1]*d1*INV_SQRT3,
                           R[2]*d2*INV_SQRT3, R[3]*d3*INV_SQRT3);
    }

    float* b1base = &g_b1[r*36];
    // p01_1 : R3 * x0s * u  -> b1 channels 0..3
    radial(3, rbf, R, sw1, sb1, sw2, sb2);
    {
        float m[12];
#pragma unroll
        for (int c = 0; c < 4; c++) {
            float t = R[c] * xs[c];
            m[c*3+0]=t*u[0]; m[c*3+1]=t*u[1]; m[c*3+2]=t*u[2];
        }
        red4(b1base+0, m[0],m[1],m[2],m[3]);
        red4(b1base+4, m[4],m[5],m[6],m[7]);
        red4(b1base+8, m[8],m[9],m[10],m[11]);
    }
    // p10_1 : R4 * x1s -> b1 channels 4..7
    radial(4, rbf, R, sw1, sb1, sw2, sb2);
    {
        float m[12];
#pragma unroll
        for (int c = 0; c < 4; c++) {
            m[c*3+0]=R[c]*x1[c*3+0]; m[c*3+1]=R[c]*x1[c*3+1]; m[c*3+2]=R[c]*x1[c*3+2];
        }
        red4(b1base+12, m[0],m[1],m[2],m[3]);
        red4(b1base+16, m[4],m[5],m[6],m[7]);
        red4(b1base+20, m[8],m[9],m[10],m[11]);
    }
    // p11_1 : R6 * cross(x1s, u) / sqrt2 -> b1 channels 8..11
    radial(6, rbf, R, sw1, sb1, sw2, sb2);
    {
        float m[12];
#pragma unroll
        for (int c = 0; c < 4; c++) {
            float ax = x1[c*3+0], ay = x1[c*3+1], az = x1[c*3+2];
            float cx = ay*u[2] - az*u[1];
            float cy = az*u[0] - ax*u[2];
            float cz = ax*u[1] - ay*u[0];
            float t = R[c] * INV_SQRT2;
            m[c*3+0]=t*cx; m[c*3+1]=t*cy; m[c*3+2]=t*cz;
        }
        red4(b1base+24, m[0],m[1],m[2],m[3]);
        red4(b1base+28, m[4],m[5],m[6],m[7]);
        red4(b1base+32, m[8],m[9],m[10],m[11]);
    }
}

// node update 2: si3 + gate   (f0: 8 -> 4 ;  f1: 12ch -> 4ch)
__global__ void k_node2(const float* __restrict__ w30, const float* __restrict__ w31) {
    int n = blockIdx.x * blockDim.x + threadIdx.x;
    if (n >= N_NODES) return;
    float b0[8];
    {
        float4 t0 = ((const float4*)g_b0)[n*2+0];
        float4 t1 = ((const float4*)g_b0)[n*2+1];
        b0[0]=t0.x; b0[1]=t0.y; b0[2]=t0.z; b0[3]=t0.w;
        b0[4]=t1.x; b0[5]=t1.y; b0[6]=t1.z; b0[7]=t1.w;
    }
    float out0[4];
#pragma unroll
    for (int o = 0; o < 4; o++) {
        float sacc = 0.f;
#pragma unroll
        for (int i = 0; i < 8; i++) sacc = fmaf(__ldg(&w30[o*8+i]), b0[i], sacc);
        out0[o] = sacc * sigmoidf(sacc);
    }
    ((float4*)g_x0c)[n] = make_float4(out0[0], out0[1], out0[2], out0[3]);

    float b1[36];
#pragma unroll
    for (int q = 0; q < 9; q++) {
        float4 t = ((const float4*)g_b1)[n*9+q];
        b1[q*4+0]=t.x; b1[q*4+1]=t.y; b1[q*4+2]=t.z; b1[q*4+3]=t.w;
    }
    float out1[12];
#pragma unroll
    for (int o = 0; o < 4; o++) {
        float vx = 0.f, vy = 0.f, vz = 0.f;
#pragma unroll
        for (int i = 0; i < 12; i++) {
            float w = __ldg(&w31[o*12+i]);
            vx = fmaf(w, b1[i*3+0], vx);
            vy = fmaf(w, b1[i*3+1], vy);
            vz = fmaf(w, b1[i*3+2], vz);
        }
        float nrm = sqrtf(vx*vx + vy*vy + vz*vz);
        float gt = sigmoidf(nrm);
        out1[o*3+0]=vx*gt; out1[o*3+1]=vy*gt; out1[o*3+2]=vz*gt;
    }
    ((float4*)g_x1c)[n*3+0] = make_float4(out1[0], out1[1], out1[2],  out1[3]);
    ((float4*)g_x1c)[n*3+1] = make_float4(out1[4], out1[5], out1[6],  out1[7]);
    ((float4*)g_x1c)[n*3+2] = make_float4(out1[8], out1[9], out1[10], out1[11]);
}

// Layer 3 edges: paths 7, 8
__global__ void k_edge3(const float* __restrict__ pos,
                        const int* __restrict__ snd, const int* __restrict__ rcv,
                        const float* __restrict__ rw1, const float* __restrict__ rb1,
                        const float* __restrict__ rw2, const float* __restrict__ rb2) {
    LOAD_RADIAL_SMEM(rw1, rb1, rw2, rb2);
    int e = blockIdx.x * blockDim.x + threadIdx.x;
    if (e >= N_EDGES) return;
    int s = snd[e], r = rcv[e];
    float u[3], rbf[8];
    edge_geom(pos, s, r, u, rbf);

    float4 x0 = ((const float4*)g_x0c)[s];
    float R[4];
    radial(7, rbf, R, sw1, sb1, sw2, sb2);
    red4(&g_c0[r*8], R[0]*x0.x, R[1]*x0.y, R[2]*x0.z, R[3]*x0.w);

    radial(8, rbf, R, sw1, sb1, sw2, sb2);
    float4 t0 = ((const float4*)g_x1c)[s*3+0];
    float4 t1 = ((const float4*)g_x1c)[s*3+1];
    float4 t2 = ((const float4*)g_x1c)[s*3+2];
    float d0 = t0.x*u[0] + t0.y*u[1] + t0.z*u[2];
    float d1 = t0.w*u[0] + t1.x*u[1] + t1.y*u[2];
    float d2 = t1.z*u[0] + t1.w*u[1] + t2.x*u[2];
    float d3 = t2.y*u[0] + t2.z*u[1] + t2.w*u[2];
    red4(&g_c0[r*8+4], R[0]*d0*INV_SQRT3, R[1]*d1*INV_SQRT3,
                       R[2]*d2*INV_SQRT3, R[3]*d3*INV_SQRT3);
}

// readout: per-node si4 + silu, warp-reduce over 32 nodes/graph, apply w_out
__global__ void k_final(const float* __restrict__ w4, const float* __restrict__ wout,
                        float* __restrict__ out) {
    int gw = (blockIdx.x * blockDim.x + threadIdx.x) >> 5;
    int lane = threadIdx.x & 31;
    if (gw >= N_GRAPH) return;
    int n = gw * NPG + lane;
    float c0[8];
    {
        float4 t0 = ((const float4*)g_c0)[n*2+0];
        float4 t1 = ((const float4*)g_c0)[n*2+1];
        c0[0]=t0.x; c0[1]=t0.y; c0[2]=t0.z; c0[3]=t0.w;
        c0[4]=t1.x; c0[5]=t1.y; c0[6]=t1.z; c0[7]=t1.w;
    }
    float f[4];
#pragma unroll
    for (int o = 0; o < 4; o++) {
        float sacc = 0.f;
#pragma unroll
        for (int i = 0; i < 8; i++) sacc = fmaf(__ldg(&w4[o*8+i]), c0[i], sacc);
        f[o] = sacc * sigmoidf(sacc);
    }
#pragma unroll
    for (int o = 0; o < 4; o++) {
#pragma unroll
        for (int off = 16; off > 0; off >>= 1)
            f[o] += __shfl_xor_sync(0xFFFFFFFFu, f[o], off);
    }
    if (lane < 8) {
        float acc = 0.f;
#pragma unroll
        for (int o = 0; o < 4; o++) acc = fmaf(__ldg(&wout[lane*4+o]), f[o], acc);
        out[gw*8 + lane] = acc;
    }
}

// ---------------- launch ----------------------------------------------------
extern "C" void kernel_launch(void* const* d_in, const int* in_sizes, int n_in,
                              void* d_out, int out_size) {
    const float* pos   = (const float*)d_in[0];
    const float* nf    = (const float*)d_in[1];
    const float* w_si1 = (const float*)d_in[2];
    const float* w20   = (const float*)d_in[3];
    const float* w21   = (const float*)d_in[4];
    const float* w30   = (const float*)d_in[5];
    const float* w31   = (const float*)d_in[6];
    const float* w4    = (const float*)d_in[7];
    const float* wout  = (const float*)d_in[8];
    const float* rw1   = (const float*)d_in[9];
    const float* rb1   = (const float*)d_in[10];
    const float* rw2   = (const float*)d_in[11];
    const float* rb2   = (const float*)d_in[12];
    const int*   snd   = (const int*)d_in[13];
    const int*   rcv   = (const int*)d_in[14];
    float* out = (float*)d_out;

    const int TB = 256;
    k_init<<<2048, TB>>>(nf, w_si1);
    k_edge1<<<N_EDGES / TB, TB>>>(pos, snd, rcv, rw1, rb1, rw2, rb2);
    k_node1<<<N_NODES / TB, TB>>>(w20, w21);
    k_edge2<<<N_EDGES / TB, TB>>>(pos, snd, rcv, rw1, rb1, rw2, rb2);
    k_node2<<<N_NODES / TB, TB>>>(w30, w31);
    k_edge3<<<N_EDGES / TB, TB>>>(pos, snd, rcv, rw1, rb1, rw2, rb2);
    k_final<<<(N_GRAPH * 32) / TB, TB>>>(w4, wout, out);
}